// round 3
// baseline (speedup 1.0000x reference)
#include <cuda_runtime.h>
#include <cstdint>

// Problem constants
#define Bv 2
#define Lv 5
#define Nv 10          // B*L
#define Hv 100
#define Wv 352
#define Cv 256
#define C4v 64         // C / 4
#define RTE 2
#define STRIP 8        // pixels per 64-thread group

// Scratch (allocation-free rule: __device__ global)
__device__ float g_pe[Nv * Cv];     // per-(b,l) projected embedding

// ---------------------------------------------------------------------------
// Kernel A: pe[n][c] = dot(emb[idx[n]], lin_W[c]) + lin_b[c]
// One warp per output element; lanes split k; shfl reduce. ~2 us.
// ---------------------------------------------------------------------------
__global__ void __launch_bounds__(256) pe_kernel(const int* __restrict__ prior,
                                                 const float* __restrict__ emb,
                                                 const float* __restrict__ linW,
                                                 const float* __restrict__ linb) {
    const int wg   = blockIdx.x * 8 + (threadIdx.x >> 5);  // 0..2559
    const int lane = threadIdx.x & 31;
    const int n = wg >> 8;
    const int c = wg & 255;
    const int idx = __ldg(&prior[n]) * RTE;

    const float4* wrow = reinterpret_cast<const float4*>(linW + (size_t)c * Cv);
    const float4* erow = reinterpret_cast<const float4*>(emb + (size_t)idx * Cv);
    const int k4 = lane * 2;
    float4 w0 = __ldg(&wrow[k4]);
    float4 w1 = __ldg(&wrow[k4 + 1]);
    float4 e0 = __ldg(&erow[k4]);
    float4 e1 = __ldg(&erow[k4 + 1]);

    float acc = w0.x * e0.x + w0.y * e0.y + w0.z * e0.z + w0.w * e0.w
              + w1.x * e1.x + w1.y * e1.y + w1.z * e1.z + w1.w * e1.w;
#pragma unroll
    for (int off = 16; off > 0; off >>= 1)
        acc += __shfl_xor_sync(0xffffffffu, acc, off);

    if (lane == 0) g_pe[n * Cv + c] = acc + __ldg(&linb[c]);
}

// ---------------------------------------------------------------------------
// Kernel B: fused bilinear warp + pe broadcast-add, strip-processed.
// Block = 256 thr = 4 groups of 64; group owns chunk lane c4 and loops over
// STRIP=8 consecutive pixels (pe+theta amortized across the strip).
// Grid = (Wv/(4*STRIP)=11, Hv, Nv).
// ---------------------------------------------------------------------------
__global__ void __launch_bounds__(256) warp_kernel(const float* __restrict__ x,
                                                   const float* __restrict__ scm,
                                                   float* __restrict__ out) {
    const int n = blockIdx.z;
    const int h = blockIdx.y;
    const int g = threadIdx.x >> 6;            // group 0..3
    const int c4 = threadIdx.x & 63;           // float4 chunk 0..63
    const int wbase = blockIdx.x * (4 * STRIP) + g * STRIP;

    // --- theta from scm, inline (uniform per group; amortized over strip) ---
    const float* s = scm + n * 16;
    const float inv_vd = 1.0f / 1.6f;                 // 1/(VOXEL*DOWNSAMPLE)
    const float m00 = __ldg(&s[0]), m01 = __ldg(&s[1]), m02 = __ldg(&s[3]) * inv_vd;
    const float m10 = __ldg(&s[4]), m11 = __ldg(&s[5]), m12 = __ldg(&s[7]) * inv_vd;
    const float t0 = 50.0f  - (m00 * 50.0f + m01 * 176.0f) + m02;
    const float t1 = 176.0f - (m10 * 50.0f + m11 * 176.0f) + m12;
    const float A00 = m00 * 175.5f, A01 = m01 * 49.5f;
    const float A02 = A00 + A01 + t0;
    const float A10 = m10 * 175.5f, A11 = m11 * 49.5f;
    const float A12 = A10 + A11 + t1;
    const float na = 2.0f / 351.0f, nb = 2.0f / 99.0f;
    const float d00 = na * A00, d01 = na * A01, d02 = na * A02 - 1.0f;
    const float d10 = nb * A10, d11 = nb * A11, d12 = nb * A12 - 1.0f;
    const float rdet = 1.0f / (d00 * d11 - d01 * d10);
    const float th0 = d11 * rdet;
    const float th1 = -d01 * rdet;
    const float th2 = (d01 * d12 - d11 * d02) * rdet;
    const float th3 = -d10 * rdet;
    const float th4 = d00 * rdet;
    const float th5 = (d10 * d02 - d00 * d12) * rdet;

    const float gy = fmaf((float)h, 2.0f / 99.0f, -1.0f);
    // terms independent of w
    const float cx = fmaf(th1, gy, th2);   // ix = (th0*gx + cx + 1)*175.5
    const float cy = fmaf(th4, gy, th5);   // iy = (th3*gx + cy + 1)*49.5

    // pe chunk held in registers for the whole strip
    const float4 p = __ldg(&reinterpret_cast<const float4*>(g_pe)[n * C4v + c4]);

    const float4* __restrict__ base =
        reinterpret_cast<const float4*>(x) + (size_t)n * (Hv * Wv * C4v);
    float4* __restrict__ outrow =
        reinterpret_cast<float4*>(out) + ((size_t)n * Hv + h) * Wv * C4v;

#pragma unroll 2
    for (int i = 0; i < STRIP; i++) {
        const int w = wbase + i;
        const float gx = fmaf((float)w, 2.0f / 351.0f, -1.0f);
        const float ix = (fmaf(th0, gx, cx) + 1.0f) * 175.5f;
        const float iy = (fmaf(th3, gx, cy) + 1.0f) * 49.5f;

        const float x0f = floorf(ix), y0f = floorf(iy);
        const float wx1 = ix - x0f, wx0 = 1.0f - wx1;
        const float wy1 = iy - y0f, wy0 = 1.0f - wy1;

        const bool vx0 = (x0f >= 0.0f) & (x0f <= 351.0f);
        const bool vx1 = (x0f + 1.0f >= 0.0f) & (x0f + 1.0f <= 351.0f);
        const bool vy0 = (y0f >= 0.0f) & (y0f <= 99.0f);
        const bool vy1 = (y0f + 1.0f >= 0.0f) & (y0f + 1.0f <= 99.0f);

        const float w00 = (vx0 & vy0) ? wx0 * wy0 : 0.0f;
        const float w10 = (vx1 & vy0) ? wx1 * wy0 : 0.0f;
        const float w01 = (vx0 & vy1) ? wx0 * wy1 : 0.0f;
        const float w11 = (vx1 & vy1) ? wx1 * wy1 : 0.0f;
        const float wsum = w00 + w10 + w01 + w11;

        const int x0 = (int)fminf(fmaxf(x0f, 0.0f), 351.0f);
        const int x1 = (int)fminf(fmaxf(x0f + 1.0f, 0.0f), 351.0f);
        const int y0 = (int)fminf(fmaxf(y0f, 0.0f), 99.0f);
        const int y1 = (int)fminf(fmaxf(y0f + 1.0f, 0.0f), 99.0f);

        // int32 offsets (max ~22.5M float4, fits easily)
        const int r0o = y0 * Wv * C4v + c4;
        const int r1o = y1 * Wv * C4v + c4;
        const float4 a = __ldg(&base[r0o + x0 * C4v]);
        const float4 b = __ldg(&base[r0o + x1 * C4v]);
        const float4 c = __ldg(&base[r1o + x0 * C4v]);
        const float4 d = __ldg(&base[r1o + x1 * C4v]);

        float4 r;
        r.x = fmaf(w00, a.x, fmaf(w10, b.x, fmaf(w01, c.x, fmaf(w11, d.x, wsum * p.x))));
        r.y = fmaf(w00, a.y, fmaf(w10, b.y, fmaf(w01, c.y, fmaf(w11, d.y, wsum * p.y))));
        r.z = fmaf(w00, a.z, fmaf(w10, b.z, fmaf(w01, c.z, fmaf(w11, d.z, wsum * p.z))));
        r.w = fmaf(w00, a.w, fmaf(w10, b.w, fmaf(w01, c.w, fmaf(w11, d.w, wsum * p.w))));

        __stcs(&outrow[w * C4v + c4], r);   // streaming store: never re-read
    }
}

// ---------------------------------------------------------------------------
// Launch. Inputs (metadata order): x, prior_encoding, mask(unused), scm,
// lin_W, lin_b, emb_table. Output: (B,L,H,W,C) float32.
// ---------------------------------------------------------------------------
extern "C" void kernel_launch(void* const* d_in, const int* in_sizes, int n_in,
                              void* d_out, int out_size) {
    (void)in_sizes; (void)n_in; (void)out_size;
    const float* x     = (const float*)d_in[0];
    const int*   prior = (const int*)d_in[1];
    const float* scm   = (const float*)d_in[3];
    const float* linW  = (const float*)d_in[4];
    const float* linb  = (const float*)d_in[5];
    const float* emb   = (const float*)d_in[6];
    float* out = (float*)d_out;

    pe_kernel<<<320, 256>>>(prior, emb, linW, linb);
    warp_kernel<<<dim3(Wv / (4 * STRIP), Hv, Nv), 256>>>(x, scm, out);
}